// round 1
// baseline (speedup 1.0000x reference)
#include <cuda_runtime.h>
#include <cuda_bf16.h>

#define BB 4
#define NN 2048
#define PARAM_G 0.125f
#define VIRUS_DEATH 8e-05f

// Scratch (allocation-free rule: __device__ globals)
__device__ float g_colsum[BB * NN];
__device__ float g_m[BB];

// ---------------------------------------------------------------------------
// Kernel 0: zero the column-sum scratch (must be reset every graph replay)
// ---------------------------------------------------------------------------
__global__ void zero_kernel() {
    int t = blockIdx.x * blockDim.x + threadIdx.x;
    if (t < BB * NN) g_colsum[t] = 0.0f;
}

// ---------------------------------------------------------------------------
// Kernel 1: col_sum[b][j] = sum_{i != j} mob[b][i][j]
// Thread = column j (coalesced), each block covers a 128-row chunk.
// ---------------------------------------------------------------------------
__global__ void __launch_bounds__(256) colsum_kernel(const float* __restrict__ mob) {
    const int j  = blockIdx.x * 256 + threadIdx.x;
    const int b  = blockIdx.z;
    const int i0 = blockIdx.y * (NN / 16);
    const float* base = mob + (size_t)b * NN * NN;
    float s = 0.0f;
#pragma unroll 8
    for (int i = i0; i < i0 + NN / 16; ++i) {
        float v = base[(size_t)i * NN + j];
        s += (i == j) ? 0.0f : v;
    }
    atomicAdd(&g_colsum[b * NN + j], s);
}

// ---------------------------------------------------------------------------
// Kernel 2: per batch, fai = sum(col_sum), tau = sum(S+I+R), m = fai/tau
// ---------------------------------------------------------------------------
__global__ void __launch_bounds__(256) m_kernel(const float* __restrict__ SIR) {
    const int b = blockIdx.x;
    const int t = threadIdx.x;
    const float4* sir4 = (const float4*)(SIR + (size_t)b * NN * 4);
    float fai = 0.0f, tau = 0.0f;
    for (int j = t; j < NN; j += 256) {
        fai += g_colsum[b * NN + j];
        float4 s = sir4[j];
        tau += s.x + s.y + s.z;
    }
#pragma unroll
    for (int o = 16; o; o >>= 1) {
        fai += __shfl_down_sync(0xFFFFFFFFu, fai, o);
        tau += __shfl_down_sync(0xFFFFFFFFu, tau, o);
    }
    __shared__ float shF[8], shT[8];
    const int w = t >> 5, l = t & 31;
    if (l == 0) { shF[w] = fai; shT[w] = tau; }
    __syncthreads();
    if (t == 0) {
        float F = 0.0f, T = 0.0f;
#pragma unroll
        for (int k = 0; k < 8; ++k) { F += shF[k]; T += shT[k]; }
        g_m[b] = F / T;
    }
}

// ---------------------------------------------------------------------------
// Kernel 3: main streaming pass. One warp per row i.
//  - streams mob/sps rows (float4), zeroes diagonal
//  - writes arrive2 interleaved (sps_m, P) as two float4 stores per float4-pair
//  - accumulates F*S, F*I, F*R against shared-staged SIR (the P@X matvec)
//  - lane 0 emits Ht_SIR (6) + arrive1 (4) per node
// Output layout: [Ht_SIR (B*N*6)] [arrive1 (B*N*4)] [arrive2 (B*N*N*2)]
// ---------------------------------------------------------------------------
__global__ void __launch_bounds__(256) main_kernel(
    const float* __restrict__ param_b, const float* __restrict__ contact,
    const float* __restrict__ mob, const float* __restrict__ SIR,
    const float* __restrict__ sps, const float* __restrict__ birth,
    const float* __restrict__ death, float* __restrict__ out)
{
    __shared__ float4 sir_sh[NN];   // (S, I, R, I_sum) per node, 32 KB

    const int b = blockIdx.y;
    const int t = threadIdx.x;

    const float4* sir4 = (const float4*)(SIR + (size_t)b * NN * 4);
    for (int j = t; j < NN; j += 256) sir_sh[j] = sir4[j];
    __syncthreads();

    const int wid  = t >> 5;
    const int lane = t & 31;
    const int i    = blockIdx.x * 8 + wid;

    const float rcs = 1.0f / g_colsum[b * NN + i];
    const float m_b = g_m[b];

    const float4* mobr = (const float4*)(mob + ((size_t)b * NN + i) * NN);
    const float4* spsr = (const float4*)(sps + ((size_t)b * NN + i) * NN);
    const size_t OFF2 = (size_t)BB * NN * 6 + (size_t)BB * NN * 4;
    float4* out2 = (float4*)(out + OFF2 + ((size_t)b * NN + i) * (size_t)NN * 2);

    float fS = 0.0f, fI = 0.0f, fR = 0.0f;

#pragma unroll 4
    for (int k = lane; k < NN / 4; k += 32) {
        float4 f  = mobr[k];
        float4 sp = spsr[k];
        const int j0 = k * 4;
        if (j0     == i) { f.x = 0.0f; sp.x = 0.0f; }
        if (j0 + 1 == i) { f.y = 0.0f; sp.y = 0.0f; }
        if (j0 + 2 == i) { f.z = 0.0f; sp.z = 0.0f; }
        if (j0 + 3 == i) { f.w = 0.0f; sp.w = 0.0f; }

        float4 s0 = sir_sh[j0];
        float4 s1 = sir_sh[j0 + 1];
        float4 s2 = sir_sh[j0 + 2];
        float4 s3 = sir_sh[j0 + 3];

        fS += f.x * s0.x + f.y * s1.x + f.z * s2.x + f.w * s3.x;
        fI += f.x * s0.y + f.y * s1.y + f.z * s2.y + f.w * s3.y;
        fR += f.x * s0.z + f.y * s1.z + f.z * s2.z + f.w * s3.z;

        out2[2 * k]     = make_float4(sp.x, f.x * rcs, sp.y, f.y * rcs);
        out2[2 * k + 1] = make_float4(sp.z, f.z * rcs, sp.w, f.w * rcs);
    }

#pragma unroll
    for (int o = 16; o; o >>= 1) {
        fS += __shfl_down_sync(0xFFFFFFFFu, fS, o);
        fI += __shfl_down_sync(0xFFFFFFFFu, fI, o);
        fR += __shfl_down_sync(0xFFFFFFFFu, fR, o);
    }

    if (lane == 0) {
        const float4 sir = sir_sh[i];
        const float S = sir.x, I = sir.y, R = sir.z, Isum = sir.w;
        const float pop = S + I + R;
        const float pb  = param_b[b * NN + i];
        const float ct  = contact[b * NN + i];
        const float dth = death[i];
        const float brt = birth[i];

        const float fluxS = m_b * rcs * fS;
        const float fluxI = m_b * rcs * fI;
        const float fluxR = m_b * rcs * fR;

        const float I_new  = S / pop * pb * ct * I;
        const float R_t    = R + PARAM_G * I - dth * R - m_b * R + fluxR;
        const float I_t    = I + I_new - dth * I - PARAM_G * I - VIRUS_DEATH * I - m_b * I + fluxI;
        const float S_t    = S - I_new - dth * S + brt * pop - m_b * S + fluxS;
        const float Isum_t = Isum + I_new;
        const float R0     = pb * ct / (dth + PARAM_G + VIRUS_DEATH + m_b);
        const float W      = pb * ct - dth - PARAM_G - VIRUS_DEATH;

        float* ht = out + (size_t)(b * NN + i) * 6;
        ht[0] = R0;  ht[1] = I_new; ht[2] = S_t;
        ht[3] = I_t; ht[4] = R_t;   ht[5] = Isum_t;

        float* a1 = out + (size_t)BB * NN * 6 + (size_t)(b * NN + i) * 4;
        a1[0] = W; a1[1] = m_b; a1[2] = I; a1[3] = pop;
    }
}

// ---------------------------------------------------------------------------
extern "C" void kernel_launch(void* const* d_in, const int* in_sizes, int n_in,
                              void* d_out, int out_size) {
    const float* param_b = (const float*)d_in[0];
    const float* contact = (const float*)d_in[1];
    const float* mob     = (const float*)d_in[2];
    const float* SIR     = (const float*)d_in[3];
    const float* sps     = (const float*)d_in[4];
    const float* birth   = (const float*)d_in[5];
    const float* death   = (const float*)d_in[6];
    float* out = (float*)d_out;

    zero_kernel<<<(BB * NN + 255) / 256, 256>>>();
    colsum_kernel<<<dim3(NN / 256, 16, BB), 256>>>(mob);
    m_kernel<<<BB, 256>>>(SIR);
    main_kernel<<<dim3(NN / 8, BB), 256>>>(param_b, contact, mob, SIR, sps,
                                           birth, death, out);
}